// round 3
// baseline (speedup 1.0000x reference)
#include <cuda_runtime.h>
#include <math.h>
#include <stdint.h>

// ---------------- dimensions ----------------
#define NB   32
#define C0   2
#define H0   400
#define W0   600
#define KH1  10
#define KW1  11
#define H1   50
#define W1   66
#define OC1  64
#define POS1 (NB*H1*W1)          // 105600
#define K1   (KH1*KW1*C0)        // 220
#define H2   5
#define W2   6
#define POS2 (NB*H2*W2)          // 960
#define K2   (12*12*64)          // 9216
#define DD   64
#define KE   512
#define TH   50
#define TW   60
#define POSD (NB*TH*TW)          // 96000
#define NT1  (12*12*64)          // 9216
#define NT2  (10*11*2)           // 220
#define OHH  400
#define OWW  540
#define RECON_N (NB*2*OHH*OWW)   // 13824000

// ---------------- scratch ----------------
__device__ float g_x   [NB*H0*W0*C0];     // x NHWC
__device__ float g_A1  [(size_t)POS1*K1]; // im2col conv1
__device__ float g_h1  [(size_t)POS1*OC1];
__device__ float g_col [(size_t)POS2*K2]; // shared im2col for 5x6 convs
__device__ float g_hA  [POS2*128];
__device__ float g_hB  [POS2*128];
__device__ float g_t64 [POS2*64];
__device__ float g_z   [POS2*64];
__device__ float g_q   [POS2*64];
__device__ float g_Y1  [(size_t)POS2*NT1];
__device__ float g_t1  [(size_t)POSD*64];
__device__ float g_Y2  [(size_t)POSD*NT2];
__device__ float g_w1t [K1*OC1];
__device__ float g_w2t [K2*128];
__device__ float g_w3t [9*128*128];
__device__ float g_er1t[2*9*128*64];
__device__ float g_er2t[2*64*128];
__device__ float g_pret[128*64];
__device__ float g_d1t [9*64*128];
__device__ float g_dr1t[2*9*128*64];
__device__ float g_dr2t[2*64*128];
__device__ float g_tw1t[128*NT1];
__device__ float g_tw2t[64*NT2];
__device__ float g_esq [KE];
__device__ int   g_counts[KE];
__device__ float g_sqacc[1];
__device__ int   g_idx [POS2];

// ---------------- weight transpose (conv layout) ----------------
// w[oc][ic][kh][kw] -> wT[((kh*KW+kw)*Cin+ic)*Cout+oc]
__global__ void wtrans_kernel(const float* __restrict__ w, float* __restrict__ wT,
                              int Cout, int Cin, int KH, int KW) {
    int t = blockIdx.x * blockDim.x + threadIdx.x;
    int total = Cout * Cin * KH * KW;
    if (t >= total) return;
    int oc = t % Cout;
    int r  = t / Cout;
    int ic = r % Cin;
    int kk = r / Cin;
    int kh = kk / KW, kw = kk % KW;
    wT[t] = w[((oc*Cin + ic)*KH + kh)*KW + kw];
}

// conv-transpose layout: w[ic][oc][kh][kw] -> wT[ic*(KH*KW*Cout) + kk*Cout + oc]
__global__ void wtransT_kernel(const float* __restrict__ w, float* __restrict__ wT,
                               int Cin, int Cout, int KH, int KW) {
    int t = blockIdx.x * blockDim.x + threadIdx.x;
    int total = Cin * Cout * KH * KW;
    if (t >= total) return;
    int oc = t % Cout;
    int r  = t / Cout;
    int kk = r % (KH*KW);
    int ic = r / (KH*KW);
    int kh = kk / KW, kw = kk % KW;
    wT[t] = w[((ic*Cout + oc)*KH + kh)*KW + kw];
}

// ---------------- NCHW -> NHWC ----------------
__global__ void nchw2nhwc_kernel(const float* __restrict__ in, float* __restrict__ out,
                                 int B, int C, int H, int W) {
    long t = (long)blockIdx.x * blockDim.x + threadIdx.x;
    long total = (long)B*C*H*W;
    if (t >= total) return;
    int c = t % C; long r = t / C;
    int w = r % W; r /= W;
    int h = r % H; int b = (int)(r / H);
    out[t] = in[(((long)b*C + c)*H + h)*W + w];
}

// ---------------- im2col (NHWC input) ----------------
__global__ void im2col_kernel(const float* __restrict__ in, float* __restrict__ out,
                              int B,int H,int W,int C,int KH,int KW,int SH,int SW,
                              int PH,int PW,int OH,int OW,int relu,long total) {
    long t = (long)blockIdx.x * blockDim.x + threadIdx.x;
    if (t >= total) return;
    int KC = KH*KW*C;
    int k = (int)(t % KC);
    long pos = t / KC;
    int ic = k % C; int r = k / C;
    int kw = r % KW; int kh = r / KW;
    int ow = (int)(pos % OW); long r2 = pos / OW;
    int oh = (int)(r2 % OH); int b = (int)(r2 / OH);
    int ih = oh*SH - PH + kh;
    int iw = ow*SW - PW + kw;
    float v = 0.f;
    if (ih >= 0 && ih < H && iw >= 0 && iw < W) {
        v = in[(((long)(b*H + ih))*W + iw)*C + ic];
        if (relu) v = fmaxf(v, 0.f);
    }
    out[t] = v;
}

// ---------------- tiled fp32 GEMM: C = [relu]( A[M,K]@B[K,N] + bias + addC*C ) ----------------
__global__ __launch_bounds__(128)
void gemm_kernel(const float* __restrict__ A, const float* __restrict__ B,
                 float* __restrict__ C, int M, int N, int K,
                 const float* __restrict__ bias, int reluOut, int reluA, int addC)
{
    __shared__ float As[64][17];
    __shared__ float Bs[16][64];
    int m0 = blockIdx.y * 64;
    int n0 = blockIdx.x * 64;
    int tid = threadIdx.x;
    int ty = tid >> 4;   // 0..7
    int tx = tid & 15;   // 0..15
    float acc[8][4];
#pragma unroll
    for (int i = 0; i < 8; i++)
#pragma unroll
        for (int j = 0; j < 4; j++) acc[i][j] = 0.f;

    for (int k0 = 0; k0 < K; k0 += 16) {
#pragma unroll
        for (int r = 0; r < 8; r++) {
            int t = tid + r*128;
            int m = t >> 4, k = t & 15;
            int gm = m0 + m, gk = k0 + k;
            float v = (gm < M && gk < K) ? A[(size_t)gm*K + gk] : 0.f;
            if (reluA) v = fmaxf(v, 0.f);
            As[m][k] = v;
        }
#pragma unroll
        for (int r = 0; r < 8; r++) {
            int t = tid + r*128;
            int k = t >> 6;      // 0..15
            int n = t & 63;
            int gk = k0 + k, gn = n0 + n;
            Bs[k][n] = (gk < K && gn < N) ? B[(size_t)gk*N + gn] : 0.f;
        }
        __syncthreads();
#pragma unroll
        for (int kk = 0; kk < 16; kk++) {
            float a[8], b[4];
#pragma unroll
            for (int i = 0; i < 8; i++) a[i] = As[ty*8 + i][kk];
#pragma unroll
            for (int j = 0; j < 4; j++) b[j] = Bs[kk][tx*4 + j];
#pragma unroll
            for (int i = 0; i < 8; i++)
#pragma unroll
                for (int j = 0; j < 4; j++) acc[i][j] = fmaf(a[i], b[j], acc[i][j]);
        }
        __syncthreads();
    }
#pragma unroll
    for (int i = 0; i < 8; i++) {
        int gm = m0 + ty*8 + i;
        if (gm >= M) continue;
#pragma unroll
        for (int j = 0; j < 4; j++) {
            int gn = n0 + tx*4 + j;
            if (gn >= N) continue;
            float v = acc[i][j];
            if (bias) v += bias[gn];
            if (addC) v += C[(size_t)gm*N + gn];
            if (reluOut) v = fmaxf(v, 0.f);
            C[(size_t)gm*N + gn] = v;
        }
    }
}

// ---------------- VQ ----------------
__global__ void esq_kernel(const float* __restrict__ emb, float* __restrict__ esq) {
    int k = threadIdx.x;
    float s = 0.f;
    const float* e = emb + k*64;
#pragma unroll
    for (int d = 0; d < 64; d++) s = fmaf(e[d], e[d], s);
    esq[k] = s;
}

__global__ void zero_kernel(int* counts, float* sqacc) {
    int t = threadIdx.x;
    counts[t] = 0;
    if (t == 0) sqacc[0] = 0.f;
}

__global__ void vq_kernel(const float* __restrict__ z, const float* __restrict__ emb,
                          const float* __restrict__ esq, int* __restrict__ idx,
                          float* __restrict__ q, int* __restrict__ counts,
                          float* __restrict__ sqacc)
{
    __shared__ float zs[64];
    __shared__ float sb[128];
    __shared__ int   si[128];
    int pos = blockIdx.x;
    int tid = threadIdx.x;
    if (tid < 64) zs[tid] = z[pos*64 + tid];
    __syncthreads();
    float best = 3.4e38f; int bi = 0x7fffffff;
    for (int k = tid; k < KE; k += 128) {
        const float* e = emb + k*64;
        float dot = 0.f;
#pragma unroll
        for (int d = 0; d < 64; d++) dot = fmaf(e[d], zs[d], dot);
        float s = esq[k] - 2.f*dot;
        if (s < best || (s == best && k < bi)) { best = s; bi = k; }
    }
    sb[tid] = best; si[tid] = bi;
    __syncthreads();
    for (int off = 64; off > 0; off >>= 1) {
        if (tid < off) {
            float s2 = sb[tid+off]; int i2 = si[tid+off];
            if (s2 < sb[tid] || (s2 == sb[tid] && i2 < si[tid])) { sb[tid] = s2; si[tid] = i2; }
        }
        __syncthreads();
    }
    int bk = si[0];
    if (tid == 0) { idx[pos] = bk; atomicAdd(&counts[bk], 1); }
    __syncthreads();
    float v = 0.f;
    if (tid < 64) {
        float qv = emb[bk*64 + tid];
        q[pos*64 + tid] = qv;
        float d = qv - zs[tid];
        v = d*d;
    }
    sb[tid] = v;
    __syncthreads();
    for (int off = 64; off > 0; off >>= 1) {
        if (tid < off) sb[tid] += sb[tid+off];
        __syncthreads();
    }
    if (tid == 0) atomicAdd(sqacc, sb[0]);
}

__global__ void finalize_kernel(const int* __restrict__ counts, const float* __restrict__ sqacc,
                                float* __restrict__ out, long outN) {
    __shared__ float sh[512];
    int tid = threadIdx.x;
    float p = (float)counts[tid] / 960.f;
    sh[tid] = p * logf(p + 1e-10f);
    __syncthreads();
    for (int off = 256; off > 0; off >>= 1) {
        if (tid < off) sh[tid] += sh[tid+off];
        __syncthreads();
    }
    if (tid == 0) {
        out[0] = 1.25f * sqacc[0] / (float)(POS2*64);
        out[outN-1] = expf(-sh[0]);
    }
}

// ---------------- convT gathers ----------------
// convT1: Y1[960][9216] -> t1[96000][64] NHWC, +bias, relu. k=12 s=10 p=1.
__global__ void gather_t1_kernel(const float* __restrict__ Y1, const float* __restrict__ bias,
                                 float* __restrict__ t1) {
    int t = blockIdx.x * blockDim.x + threadIdx.x;
    if (t >= POSD*64) return;
    int oc = t & 63;
    int pos = t >> 6;
    int ow = pos % TW; int r = pos / TW;
    int oh = r % TH; int b = r / TH;
    float acc = bias[oc];
    int lo = oh - 10;
    int ih_lo = lo <= 0 ? 0 : (lo + 9)/10;
    int ih_hi = (oh + 1)/10; if (ih_hi > 4) ih_hi = 4;
    int lw = ow - 10;
    int iw_lo = lw <= 0 ? 0 : (lw + 9)/10;
    int iw_hi = (ow + 1)/10; if (iw_hi > 5) iw_hi = 5;
    for (int ih = ih_lo; ih <= ih_hi; ih++) {
        int kh = oh + 1 - 10*ih;
        for (int iw = iw_lo; iw <= iw_hi; iw++) {
            int kw = ow + 1 - 10*iw;
            acc += Y1[(size_t)((b*5 + ih)*6 + iw)*NT1 + (kh*12 + kw)*64 + oc];
        }
    }
    t1[t] = fmaxf(acc, 0.f);
}

// convT2: Y2[96000][220] -> recon NCHW (32,2,400,540), +bias. kh=10 sh=8, kw=11 sw=9, p=1.
__global__ void gather_recon_kernel(const float* __restrict__ Y2, const float* __restrict__ bias,
                                    float* __restrict__ out) {
    long t = (long)blockIdx.x * blockDim.x + threadIdx.x;
    if (t >= (long)RECON_N) return;
    int ow = (int)(t % OWW); long r = t / OWW;
    int oh = (int)(r % OHH); r /= OHH;
    int oc = (int)(r % 2); int b = (int)(r / 2);
    float acc = bias[oc];
    int lo = oh - 8;
    int ih_lo = lo <= 0 ? 0 : (lo + 7)/8;
    int ih_hi = (oh + 1)/8; if (ih_hi > 49) ih_hi = 49;
    int lw = ow - 9;
    int iw_lo = lw <= 0 ? 0 : (lw + 8)/9;
    int iw_hi = (ow + 1)/9; if (iw_hi > 59) iw_hi = 59;
    for (int ih = ih_lo; ih <= ih_hi; ih++) {
        int kh = oh + 1 - 8*ih;
        for (int iw = iw_lo; iw <= iw_hi; iw++) {
            int kw = ow + 1 - 9*iw;
            acc += Y2[(size_t)((b*TH + ih)*TW + iw)*NT2 + (kh*11 + kw)*2 + oc];
        }
    }
    out[t] = acc;
}

// ---------------- host ----------------
static inline void launch_gemm(const float* A, const float* B, float* C,
                               int M, int N, int K, const float* bias,
                               int reluOut, int reluA, int addC) {
    dim3 grid((N + 63)/64, (M + 63)/64);
    gemm_kernel<<<grid, 128>>>(A, B, C, M, N, K, bias, reluOut, reluA, addC);
}

static inline void launch_im2col(const float* in, float* out,
                                 int B,int H,int W,int C,int KH,int KW,int SH,int SW,
                                 int PH,int PW,int OH,int OW,int relu) {
    long total = (long)B*OH*OW*KH*KW*C;
    long blocks = (total + 255)/256;
    im2col_kernel<<<(unsigned)blocks, 256>>>(in,out,B,H,W,C,KH,KW,SH,SW,PH,PW,OH,OW,relu,total);
}

static inline void launch_wtrans(const float* w, float* wT, int Cout,int Cin,int KH,int KW) {
    int total = Cout*Cin*KH*KW;
    wtrans_kernel<<<(total+255)/256, 256>>>(w, wT, Cout, Cin, KH, KW);
}

extern "C" void kernel_launch(void* const* d_in, const int* in_sizes, int n_in,
                              void* d_out, int out_size) {
    const float* x       = (const float*)d_in[0];
    const float* enc_w1  = (const float*)d_in[1];
    const float* enc_b1  = (const float*)d_in[2];
    const float* enc_w2  = (const float*)d_in[3];
    const float* enc_b2  = (const float*)d_in[4];
    const float* enc_w3  = (const float*)d_in[5];
    const float* enc_b3  = (const float*)d_in[6];
    const float* enc_rw1 = (const float*)d_in[7];
    const float* enc_rw2 = (const float*)d_in[8];
    const float* pre_w   = (const float*)d_in[9];
    const float* pre_b   = (const float*)d_in[10];
    const float* emb     = (const float*)d_in[11];
    const float* dec_w1  = (const float*)d_in[12];
    const float* dec_b1  = (const float*)d_in[13];
    const float* dec_rw1 = (const float*)d_in[14];
    const float* dec_rw2 = (const float*)d_in[15];
    const float* dec_tw1 = (const float*)d_in[16];
    const float* dec_tb1 = (const float*)d_in[17];
    const float* dec_tw2 = (const float*)d_in[18];
    const float* dec_tb2 = (const float*)d_in[19];
    float* out = (float*)d_out;

    float *p_x, *p_A1, *p_h1, *p_col, *p_hA, *p_hB, *p_t64, *p_z, *p_q;
    float *p_Y1, *p_t1, *p_Y2;
    float *p_w1t, *p_w2t, *p_w3t, *p_er1t, *p_er2t, *p_pret, *p_d1t, *p_dr1t, *p_dr2t;
    float *p_tw1t, *p_tw2t, *p_esq, *p_sqacc;
    int *p_counts, *p_idx;
    cudaGetSymbolAddress((void**)&p_x, g_x);
    cudaGetSymbolAddress((void**)&p_A1, g_A1);
    cudaGetSymbolAddress((void**)&p_h1, g_h1);
    cudaGetSymbolAddress((void**)&p_col, g_col);
    cudaGetSymbolAddress((void**)&p_hA, g_hA);
    cudaGetSymbolAddress((void**)&p_hB, g_hB);
    cudaGetSymbolAddress((void**)&p_t64, g_t64);
    cudaGetSymbolAddress((void**)&p_z, g_z);
    cudaGetSymbolAddress((void**)&p_q, g_q);
    cudaGetSymbolAddress((void**)&p_Y1, g_Y1);
    cudaGetSymbolAddress((void**)&p_t1, g_t1);
    cudaGetSymbolAddress((void**)&p_Y2, g_Y2);
    cudaGetSymbolAddress((void**)&p_w1t, g_w1t);
    cudaGetSymbolAddress((void**)&p_w2t, g_w2t);
    cudaGetSymbolAddress((void**)&p_w3t, g_w3t);
    cudaGetSymbolAddress((void**)&p_er1t, g_er1t);
    cudaGetSymbolAddress((void**)&p_er2t, g_er2t);
    cudaGetSymbolAddress((void**)&p_pret, g_pret);
    cudaGetSymbolAddress((void**)&p_d1t, g_d1t);
    cudaGetSymbolAddress((void**)&p_dr1t, g_dr1t);
    cudaGetSymbolAddress((void**)&p_dr2t, g_dr2t);
    cudaGetSymbolAddress((void**)&p_tw1t, g_tw1t);
    cudaGetSymbolAddress((void**)&p_tw2t, g_tw2t);
    cudaGetSymbolAddress((void**)&p_esq, g_esq);
    cudaGetSymbolAddress((void**)&p_sqacc, g_sqacc);
    cudaGetSymbolAddress((void**)&p_counts, g_counts);
    cudaGetSymbolAddress((void**)&p_idx, g_idx);

    // ---- weight transposes ----
    launch_wtrans(enc_w1, p_w1t, 64, 2, 10, 11);
    launch_wtrans(enc_w2, p_w2t, 128, 64, 12, 12);
    launch_wtrans(enc_w3, p_w3t, 128, 128, 3, 3);
    launch_wtrans(enc_rw1,            p_er1t,            64, 128, 3, 3);
    launch_wtrans(enc_rw1 + 64*128*9, p_er1t + 1152*64,  64, 128, 3, 3);
    launch_wtrans(enc_rw2,            p_er2t,            128, 64, 1, 1);
    launch_wtrans(enc_rw2 + 128*64,   p_er2t + 64*128,   128, 64, 1, 1);
    launch_wtrans(pre_w, p_pret, 64, 128, 1, 1);
    launch_wtrans(dec_w1, p_d1t, 128, 64, 3, 3);
    launch_wtrans(dec_rw1,            p_dr1t,            64, 128, 3, 3);
    launch_wtrans(dec_rw1 + 64*128*9, p_dr1t + 1152*64,  64, 128, 3, 3);
    launch_wtrans(dec_rw2,            p_dr2t,            128, 64, 1, 1);
    launch_wtrans(dec_rw2 + 128*64,   p_dr2t + 64*128,   128, 64, 1, 1);
    {
        int tot1 = 128*64*144;
        wtransT_kernel<<<(tot1+255)/256, 256>>>(dec_tw1, p_tw1t, 128, 64, 12, 12);
        int tot2 = 64*2*110;
        wtransT_kernel<<<(tot2+255)/256, 256>>>(dec_tw2, p_tw2t, 64, 2, 10, 11);
    }

    // ---- encoder ----
    {
        long tot = (long)NB*C0*H0*W0;
        nchw2nhwc_kernel<<<(unsigned)((tot+255)/256), 256>>>(x, p_x, NB, C0, H0, W0);
    }
    launch_im2col(p_x, p_A1, NB, H0, W0, C0, KH1, KW1, 8, 9, 1, 1, H1, W1, 0);
    launch_gemm(p_A1, p_w1t, p_h1, POS1, OC1, K1, enc_b1, 1, 0, 0);          // conv1 + relu

    launch_im2col(p_h1, p_col, NB, H1, W1, 64, 12, 12, 10, 10, 1, 1, H2, W2, 0);
    launch_gemm(p_col, p_w2t, p_hA, POS2, 128, K2, enc_b2, 1, 0, 0);         // conv2 + relu

    launch_im2col(p_hA, p_col, NB, H2, W2, 128, 3, 3, 1, 1, 1, 1, H2, W2, 0);
    launch_gemm(p_col, p_w3t, p_hB, POS2, 128, 1152, enc_b3, 0, 0, 0);       // conv3

    for (int i = 0; i < 2; i++) {                                            // enc res stack
        launch_im2col(p_hB, p_col, NB, H2, W2, 128, 3, 3, 1, 1, 1, 1, H2, W2, 1);
        launch_gemm(p_col, p_er1t + i*1152*64, p_t64, POS2, 64, 1152, 0, 1, 0, 0);
        launch_gemm(p_t64, p_er2t + i*64*128, p_hB, POS2, 128, 64, 0, 0, 0, 1);
    }
    launch_gemm(p_hB, p_pret, p_z, POS2, 64, 128, pre_b, 0, 1, 0);           // pre (relu on input)

    // ---- VQ ----
    zero_kernel<<<1, KE>>>(p_counts, p_sqacc);
    esq_kernel<<<1, KE>>>(emb, p_esq);
    vq_kernel<<<POS2, 128>>>(p_z, emb, p_esq, p_idx, p_q, p_counts, p_sqacc);
    finalize_kernel<<<1, KE>>>(p_counts, p_sqacc, out, (long)out_size);

    // ---- decoder ----
    launch_im2col(p_q, p_col, NB, H2, W2, 64, 3, 3, 1, 1, 1, 1, H2, W2, 0);
    launch_gemm(p_col, p_d1t, p_hA, POS2, 128, 576, dec_b1, 0, 0, 0);        // dec conv1

    for (int i = 0; i < 2; i++) {                                            // dec res stack
        launch_im2col(p_hA, p_col, NB, H2, W2, 128, 3, 3, 1, 1, 1, 1, H2, W2, 1);
        launch_gemm(p_col, p_dr1t + i*1152*64, p_t64, POS2, 64, 1152, 0, 1, 0, 0);
        launch_gemm(p_t64, p_dr2t + i*64*128, p_hA, POS2, 128, 64, 0, 0, 0, 1);
    }

    // convT1: GEMM (relu on input) + gather (+bias, relu)
    launch_gemm(p_hA, p_tw1t, p_Y1, POS2, NT1, 128, 0, 0, 1, 0);
    gather_t1_kernel<<<(POSD*64 + 255)/256, 256>>>(p_Y1, dec_tb1, p_t1);

    // convT2: GEMM + gather (+bias) -> recon at out+1
    launch_gemm(p_t1, p_tw2t, p_Y2, POSD, NT2, 64, 0, 0, 0, 0);
    {
        long tot = (long)RECON_N;
        gather_recon_kernel<<<(unsigned)((tot+255)/256), 256>>>(p_Y2, dec_tb2, out + 1);
    }
}

// round 4
// speedup vs baseline: 1.7091x; 1.7091x over previous
#include <cuda_runtime.h>
#include <math.h>
#include <stdint.h>

// ---------------- dimensions ----------------
#define NB   32
#define C0   2
#define H0   400
#define W0   600
#define KH1  10
#define KW1  11
#define H1   50
#define W1   66
#define OC1  64
#define POS1 (NB*H1*W1)          // 105600
#define K1   (KH1*KW1*C0)        // 220
#define H2   5
#define W2   6
#define POS2 (NB*H2*W2)          // 960
#define K2   (12*12*64)          // 9216
#define DD   64
#define KE   512
#define TH   50
#define TW   60
#define POSD (NB*TH*TW)          // 96000
#define NT1  (12*12*64)          // 9216
#define NT2  (10*11*2)           // 220
#define OHH  400
#define OWW  540
#define RECON_N (NB*2*OHH*OWW)   // 13824000

// ---------------- scratch ----------------
__device__ float g_x   [NB*H0*W0*C0];     // x NHWC
__device__ float g_A1  [(size_t)POS1*K1]; // im2col conv1
__device__ float g_h1  [(size_t)POS1*OC1];
__device__ float g_col [(size_t)POS2*K2]; // shared im2col for 5x6 convs
__device__ float g_hA  [POS2*128];
__device__ float g_hB  [POS2*128];
__device__ float g_t64 [POS2*64];
__device__ float g_z   [POS2*64];
__device__ float g_q   [POS2*64];
__device__ float g_part[8*POS2*128];      // split-K partials (max S=8, N=128)
__device__ float g_Y1  [(size_t)POS2*NT1];
__device__ float g_t1  [(size_t)POSD*64];
__device__ float g_Y2  [(size_t)POSD*NT2];
__device__ float g_w1t [K1*OC1];
__device__ float g_w2t [K2*128];
__device__ float g_w3t [9*128*128];
__device__ float g_er1t[2*9*128*64];
__device__ float g_er2t[2*64*128];
__device__ float g_pret[128*64];
__device__ float g_d1t [9*64*128];
__device__ float g_dr1t[2*9*128*64];
__device__ float g_dr2t[2*64*128];
__device__ float g_tw1t[128*NT1];
__device__ float g_tw2t[64*NT2];
__device__ float g_esq [KE];
__device__ int   g_counts[KE];
__device__ float g_sqacc[1];
__device__ int   g_idx [POS2];

// ---------------- weight transpose (conv layout) ----------------
__global__ void wtrans_kernel(const float* __restrict__ w, float* __restrict__ wT,
                              int Cout, int Cin, int KH, int KW) {
    int t = blockIdx.x * blockDim.x + threadIdx.x;
    int total = Cout * Cin * KH * KW;
    if (t >= total) return;
    int oc = t % Cout;
    int r  = t / Cout;
    int ic = r % Cin;
    int kk = r / Cin;
    int kh = kk / KW, kw = kk % KW;
    wT[t] = w[((oc*Cin + ic)*KH + kh)*KW + kw];
}

// conv-transpose layout: w[ic][oc][kh][kw] -> wT[ic*(KH*KW*Cout) + kk*Cout + oc]
__global__ void wtransT_kernel(const float* __restrict__ w, float* __restrict__ wT,
                               int Cin, int Cout, int KH, int KW) {
    int t = blockIdx.x * blockDim.x + threadIdx.x;
    int total = Cin * Cout * KH * KW;
    if (t >= total) return;
    int oc = t % Cout;
    int r  = t / Cout;
    int kk = r % (KH*KW);
    int ic = r / (KH*KW);
    int kh = kk / KW, kw = kk % KW;
    wT[t] = w[((ic*Cout + oc)*KH + kh)*KW + kw];
}

// ---------------- NCHW -> NHWC ----------------
__global__ void nchw2nhwc_kernel(const float* __restrict__ in, float* __restrict__ out,
                                 int B, int C, int H, int W) {
    long t = (long)blockIdx.x * blockDim.x + threadIdx.x;
    long total = (long)B*C*H*W;
    if (t >= total) return;
    int c = t % C; long r = t / C;
    int w = r % W; r /= W;
    int h = r % H; int b = (int)(r / H);
    out[t] = in[(((long)b*C + c)*H + h)*W + w];
}

// ---------------- im2col (NHWC input) ----------------
__global__ void im2col_kernel(const float* __restrict__ in, float* __restrict__ out,
                              int B,int H,int W,int C,int KH,int KW,int SH,int SW,
                              int PH,int PW,int OH,int OW,int relu,long total) {
    long t = (long)blockIdx.x * blockDim.x + threadIdx.x;
    if (t >= total) return;
    int KC = KH*KW*C;
    int k = (int)(t % KC);
    long pos = t / KC;
    int ic = k % C; int r = k / C;
    int kw = r % KW; int kh = r / KW;
    int ow = (int)(pos % OW); long r2 = pos / OW;
    int oh = (int)(r2 % OH); int b = (int)(r2 / OH);
    int ih = oh*SH - PH + kh;
    int iw = ow*SW - PW + kw;
    float v = 0.f;
    if (ih >= 0 && ih < H && iw >= 0 && iw < W) {
        v = in[(((long)(b*H + ih))*W + iw)*C + ic];
        if (relu) v = fmaxf(v, 0.f);
    }
    out[t] = v;
}

// ---------------- tiled fp32 GEMM: C = [relu]( A[M,K]@B[K,N] + bias + addC*C ) ----------------
__global__ __launch_bounds__(128)
void gemm_kernel(const float* __restrict__ A, const float* __restrict__ B,
                 float* __restrict__ C, int M, int N, int K,
                 const float* __restrict__ bias, int reluOut, int reluA, int addC)
{
    __shared__ float As[64][17];
    __shared__ float Bs[16][64];
    int m0 = blockIdx.y * 64;
    int n0 = blockIdx.x * 64;
    int tid = threadIdx.x;
    int ty = tid >> 4;   // 0..7
    int tx = tid & 15;   // 0..15
    float acc[8][4];
#pragma unroll
    for (int i = 0; i < 8; i++)
#pragma unroll
        for (int j = 0; j < 4; j++) acc[i][j] = 0.f;

    for (int k0 = 0; k0 < K; k0 += 16) {
#pragma unroll
        for (int r = 0; r < 8; r++) {
            int t = tid + r*128;
            int m = t >> 4, k = t & 15;
            int gm = m0 + m, gk = k0 + k;
            float v = (gm < M && gk < K) ? A[(size_t)gm*K + gk] : 0.f;
            if (reluA) v = fmaxf(v, 0.f);
            As[m][k] = v;
        }
#pragma unroll
        for (int r = 0; r < 8; r++) {
            int t = tid + r*128;
            int k = t >> 6;      // 0..15
            int n = t & 63;
            int gk = k0 + k, gn = n0 + n;
            Bs[k][n] = (gk < K && gn < N) ? B[(size_t)gk*N + gn] : 0.f;
        }
        __syncthreads();
#pragma unroll
        for (int kk = 0; kk < 16; kk++) {
            float a[8], b[4];
#pragma unroll
            for (int i = 0; i < 8; i++) a[i] = As[ty*8 + i][kk];
#pragma unroll
            for (int j = 0; j < 4; j++) b[j] = Bs[kk][tx*4 + j];
#pragma unroll
            for (int i = 0; i < 8; i++)
#pragma unroll
                for (int j = 0; j < 4; j++) acc[i][j] = fmaf(a[i], b[j], acc[i][j]);
        }
        __syncthreads();
    }
#pragma unroll
    for (int i = 0; i < 8; i++) {
        int gm = m0 + ty*8 + i;
        if (gm >= M) continue;
#pragma unroll
        for (int j = 0; j < 4; j++) {
            int gn = n0 + tx*4 + j;
            if (gn >= N) continue;
            float v = acc[i][j];
            if (bias) v += bias[gn];
            if (addC) v += C[(size_t)gm*N + gn];
            if (reluOut) v = fmaxf(v, 0.f);
            C[(size_t)gm*N + gn] = v;
        }
    }
}

// ---------------- split-K GEMM: part[s] = A[:, ks:ke] @ B[ks:ke, :] ----------------
__global__ __launch_bounds__(128)
void gemm_splitk_kernel(const float* __restrict__ A, const float* __restrict__ B,
                        float* __restrict__ Cpart, int M, int N, int K, int Kc)
{
    __shared__ float As[64][17];
    __shared__ float Bs[16][64];
    int m0 = blockIdx.y * 64;
    int n0 = blockIdx.x * 64;
    int s  = blockIdx.z;
    int kbeg = s * Kc;
    int kend = kbeg + Kc; if (kend > K) kend = K;
    int tid = threadIdx.x;
    int ty = tid >> 4;
    int tx = tid & 15;
    float acc[8][4];
#pragma unroll
    for (int i = 0; i < 8; i++)
#pragma unroll
        for (int j = 0; j < 4; j++) acc[i][j] = 0.f;

    for (int k0 = kbeg; k0 < kend; k0 += 16) {
#pragma unroll
        for (int r = 0; r < 8; r++) {
            int t = tid + r*128;
            int m = t >> 4, k = t & 15;
            int gm = m0 + m, gk = k0 + k;
            As[m][k] = (gm < M && gk < kend) ? A[(size_t)gm*K + gk] : 0.f;
        }
#pragma unroll
        for (int r = 0; r < 8; r++) {
            int t = tid + r*128;
            int k = t >> 6;
            int n = t & 63;
            int gk = k0 + k, gn = n0 + n;
            Bs[k][n] = (gk < kend && gn < N) ? B[(size_t)gk*N + gn] : 0.f;
        }
        __syncthreads();
#pragma unroll
        for (int kk = 0; kk < 16; kk++) {
            float a[8], b[4];
#pragma unroll
            for (int i = 0; i < 8; i++) a[i] = As[ty*8 + i][kk];
#pragma unroll
            for (int j = 0; j < 4; j++) b[j] = Bs[kk][tx*4 + j];
#pragma unroll
            for (int i = 0; i < 8; i++)
#pragma unroll
                for (int j = 0; j < 4; j++) acc[i][j] = fmaf(a[i], b[j], acc[i][j]);
        }
        __syncthreads();
    }
    float* Cs = Cpart + (size_t)s * M * N;
#pragma unroll
    for (int i = 0; i < 8; i++) {
        int gm = m0 + ty*8 + i;
        if (gm >= M) continue;
#pragma unroll
        for (int j = 0; j < 4; j++) {
            int gn = n0 + tx*4 + j;
            if (gn >= N) continue;
            Cs[(size_t)gm*N + gn] = acc[i][j];
        }
    }
}

__global__ void reduce_splitk_kernel(const float* __restrict__ Cpart, float* __restrict__ C,
                                     int MN, int N, int S, const float* __restrict__ bias,
                                     int reluOut, int addC)
{
    int t = blockIdx.x * blockDim.x + threadIdx.x;
    if (t >= MN) return;
    float v = 0.f;
    for (int s = 0; s < S; s++) v += Cpart[(size_t)s*MN + t];
    if (bias) v += bias[t % N];
    if (addC) v += C[t];
    if (reluOut) v = fmaxf(v, 0.f);
    C[t] = v;
}

// ---------------- VQ ----------------
__global__ void esq_kernel(const float* __restrict__ emb, float* __restrict__ esq) {
    int k = threadIdx.x;
    float s = 0.f;
    const float* e = emb + k*64;
#pragma unroll
    for (int d = 0; d < 64; d++) s = fmaf(e[d], e[d], s);
    esq[k] = s;
}

__global__ void zero_kernel(int* counts, float* sqacc) {
    int t = threadIdx.x;
    counts[t] = 0;
    if (t == 0) sqacc[0] = 0.f;
}

__global__ void vq_kernel(const float* __restrict__ z, const float* __restrict__ emb,
                          const float* __restrict__ esq, int* __restrict__ idx,
                          float* __restrict__ q, int* __restrict__ counts,
                          float* __restrict__ sqacc)
{
    __shared__ float zs[64];
    __shared__ float sb[128];
    __shared__ int   si[128];
    int pos = blockIdx.x;
    int tid = threadIdx.x;
    if (tid < 64) zs[tid] = z[pos*64 + tid];
    __syncthreads();
    float best = 3.4e38f; int bi = 0x7fffffff;
    for (int k = tid; k < KE; k += 128) {
        const float* e = emb + k*64;
        float dot = 0.f;
#pragma unroll
        for (int d = 0; d < 64; d++) dot = fmaf(e[d], zs[d], dot);
        float s = esq[k] - 2.f*dot;
        if (s < best || (s == best && k < bi)) { best = s; bi = k; }
    }
    sb[tid] = best; si[tid] = bi;
    __syncthreads();
    for (int off = 64; off > 0; off >>= 1) {
        if (tid < off) {
            float s2 = sb[tid+off]; int i2 = si[tid+off];
            if (s2 < sb[tid] || (s2 == sb[tid] && i2 < si[tid])) { sb[tid] = s2; si[tid] = i2; }
        }
        __syncthreads();
    }
    int bk = si[0];
    if (tid == 0) { idx[pos] = bk; atomicAdd(&counts[bk], 1); }
    __syncthreads();
    float v = 0.f;
    if (tid < 64) {
        float qv = emb[bk*64 + tid];
        q[pos*64 + tid] = qv;
        float d = qv - zs[tid];
        v = d*d;
    }
    sb[tid] = v;
    __syncthreads();
    for (int off = 64; off > 0; off >>= 1) {
        if (tid < off) sb[tid] += sb[tid+off];
        __syncthreads();
    }
    if (tid == 0) atomicAdd(sqacc, sb[0]);
}

__global__ void finalize_kernel(const int* __restrict__ counts, const float* __restrict__ sqacc,
                                float* __restrict__ out, long outN) {
    __shared__ float sh[512];
    int tid = threadIdx.x;
    float p = (float)counts[tid] / 960.f;
    sh[tid] = p * logf(p + 1e-10f);
    __syncthreads();
    for (int off = 256; off > 0; off >>= 1) {
        if (tid < off) sh[tid] += sh[tid+off];
        __syncthreads();
    }
    if (tid == 0) {
        out[0] = 1.25f * sqacc[0] / (float)(POS2*64);
        out[outN-1] = expf(-sh[0]);
    }
}

// ---------------- convT gathers ----------------
__global__ void gather_t1_kernel(const float* __restrict__ Y1, const float* __restrict__ bias,
                                 float* __restrict__ t1) {
    int t = blockIdx.x * blockDim.x + threadIdx.x;
    if (t >= POSD*64) return;
    int oc = t & 63;
    int pos = t >> 6;
    int ow = pos % TW; int r = pos / TW;
    int oh = r % TH; int b = r / TH;
    float acc = bias[oc];
    int lo = oh - 10;
    int ih_lo = lo <= 0 ? 0 : (lo + 9)/10;
    int ih_hi = (oh + 1)/10; if (ih_hi > 4) ih_hi = 4;
    int lw = ow - 10;
    int iw_lo = lw <= 0 ? 0 : (lw + 9)/10;
    int iw_hi = (ow + 1)/10; if (iw_hi > 5) iw_hi = 5;
    for (int ih = ih_lo; ih <= ih_hi; ih++) {
        int kh = oh + 1 - 10*ih;
        for (int iw = iw_lo; iw <= iw_hi; iw++) {
            int kw = ow + 1 - 10*iw;
            acc += Y1[(size_t)((b*5 + ih)*6 + iw)*NT1 + (kh*12 + kw)*64 + oc];
        }
    }
    t1[t] = fmaxf(acc, 0.f);
}

__global__ void gather_recon_kernel(const float* __restrict__ Y2, const float* __restrict__ bias,
                                    float* __restrict__ out) {
    long t = (long)blockIdx.x * blockDim.x + threadIdx.x;
    if (t >= (long)RECON_N) return;
    int ow = (int)(t % OWW); long r = t / OWW;
    int oh = (int)(r % OHH); r /= OHH;
    int oc = (int)(r % 2); int b = (int)(r / 2);
    float acc = bias[oc];
    int lo = oh - 8;
    int ih_lo = lo <= 0 ? 0 : (lo + 7)/8;
    int ih_hi = (oh + 1)/8; if (ih_hi > 49) ih_hi = 49;
    int lw = ow - 9;
    int iw_lo = lw <= 0 ? 0 : (lw + 8)/9;
    int iw_hi = (ow + 1)/9; if (iw_hi > 59) iw_hi = 59;
    for (int ih = ih_lo; ih <= ih_hi; ih++) {
        int kh = oh + 1 - 8*ih;
        for (int iw = iw_lo; iw <= iw_hi; iw++) {
            int kw = ow + 1 - 9*iw;
            acc += Y2[(size_t)((b*TH + ih)*TW + iw)*NT2 + (kh*11 + kw)*2 + oc];
        }
    }
    out[t] = acc;
}

// ---------------- host ----------------
static inline void launch_gemm(const float* A, const float* B, float* C,
                               int M, int N, int K, const float* bias,
                               int reluOut, int reluA, int addC) {
    dim3 grid((N + 63)/64, (M + 63)/64);
    gemm_kernel<<<grid, 128>>>(A, B, C, M, N, K, bias, reluOut, reluA, addC);
}

static inline void launch_gemm_splitk(const float* A, const float* B, float* C, float* part,
                                      int M, int N, int K, int S, const float* bias,
                                      int reluOut, int addC) {
    int Kc = (K + S - 1) / S;
    Kc = ((Kc + 15) / 16) * 16;   // multiple of 16 for the k-loop
    S  = (K + Kc - 1) / Kc;       // recompute S after rounding
    dim3 grid((N + 63)/64, (M + 63)/64, S);
    gemm_splitk_kernel<<<grid, 128>>>(A, B, part, M, N, K, Kc);
    int MN = M * N;
    reduce_splitk_kernel<<<(MN + 255)/256, 256>>>(part, C, MN, N, S, bias, reluOut, addC);
}

static inline void launch_im2col(const float* in, float* out,
                                 int B,int H,int W,int C,int KH,int KW,int SH,int SW,
                                 int PH,int PW,int OH,int OW,int relu) {
    long total = (long)B*OH*OW*KH*KW*C;
    long blocks = (total + 255)/256;
    im2col_kernel<<<(unsigned)blocks, 256>>>(in,out,B,H,W,C,KH,KW,SH,SW,PH,PW,OH,OW,relu,total);
}

static inline void launch_wtrans(const float* w, float* wT, int Cout,int Cin,int KH,int KW) {
    int total = Cout*Cin*KH*KW;
    wtrans_kernel<<<(total+255)/256, 256>>>(w, wT, Cout, Cin, KH, KW);
}

extern "C" void kernel_launch(void* const* d_in, const int* in_sizes, int n_in,
                              void* d_out, int out_size) {
    const float* x       = (const float*)d_in[0];
    const float* enc_w1  = (const float*)d_in[1];
    const float* enc_b1  = (const float*)d_in[2];
    const float* enc_w2  = (const float*)d_in[3];
    const float* enc_b2  = (const float*)d_in[4];
    const float* enc_w3  = (const float*)d_in[5];
    const float* enc_b3  = (const float*)d_in[6];
    const float* enc_rw1 = (const float*)d_in[7];
    const float* enc_rw2 = (const float*)d_in[8];
    const float* pre_w   = (const float*)d_in[9];
    const float* pre_b   = (const float*)d_in[10];
    const float* emb     = (const float*)d_in[11];
    const float* dec_w1  = (const float*)d_in[12];
    const float* dec_b1  = (const float*)d_in[13];
    const float* dec_rw1 = (const float*)d_in[14];
    const float* dec_rw2 = (const float*)d_in[15];
    const float* dec_tw1 = (const float*)d_in[16];
    const float* dec_tb1 = (const float*)d_in[17];
    const float* dec_tw2 = (const float*)d_in[18];
    const float* dec_tb2 = (const float*)d_in[19];
    float* out = (float*)d_out;

    float *p_x, *p_A1, *p_h1, *p_col, *p_hA, *p_hB, *p_t64, *p_z, *p_q, *p_part;
    float *p_Y1, *p_t1, *p_Y2;
    float *p_w1t, *p_w2t, *p_w3t, *p_er1t, *p_er2t, *p_pret, *p_d1t, *p_dr1t, *p_dr2t;
    float *p_tw1t, *p_tw2t, *p_esq, *p_sqacc;
    int *p_counts, *p_idx;
    cudaGetSymbolAddress((void**)&p_x, g_x);
    cudaGetSymbolAddress((void**)&p_A1, g_A1);
    cudaGetSymbolAddress((void**)&p_h1, g_h1);
    cudaGetSymbolAddress((void**)&p_col, g_col);
    cudaGetSymbolAddress((void**)&p_hA, g_hA);
    cudaGetSymbolAddress((void**)&p_hB, g_hB);
    cudaGetSymbolAddress((void**)&p_t64, g_t64);
    cudaGetSymbolAddress((void**)&p_z, g_z);
    cudaGetSymbolAddress((void**)&p_q, g_q);
    cudaGetSymbolAddress((void**)&p_part, g_part);
    cudaGetSymbolAddress((void**)&p_Y1, g_Y1);
    cudaGetSymbolAddress((void**)&p_t1, g_t1);
    cudaGetSymbolAddress((void**)&p_Y2, g_Y2);
    cudaGetSymbolAddress((void**)&p_w1t, g_w1t);
    cudaGetSymbolAddress((void**)&p_w2t, g_w2t);
    cudaGetSymbolAddress((void**)&p_w3t, g_w3t);
    cudaGetSymbolAddress((void**)&p_er1t, g_er1t);
    cudaGetSymbolAddress((void**)&p_er2t, g_er2t);
    cudaGetSymbolAddress((void**)&p_pret, g_pret);
    cudaGetSymbolAddress((void**)&p_d1t, g_d1t);
    cudaGetSymbolAddress((void**)&p_dr1t, g_dr1t);
    cudaGetSymbolAddress((void**)&p_dr2t, g_dr2t);
    cudaGetSymbolAddress((void**)&p_tw1t, g_tw1t);
    cudaGetSymbolAddress((void**)&p_tw2t, g_tw2t);
    cudaGetSymbolAddress((void**)&p_esq, g_esq);
    cudaGetSymbolAddress((void**)&p_sqacc, g_sqacc);
    cudaGetSymbolAddress((void**)&p_counts, g_counts);
    cudaGetSymbolAddress((void**)&p_idx, g_idx);

    // ---- weight transposes ----
    launch_wtrans(enc_w1, p_w1t, 64, 2, 10, 11);
    launch_wtrans(enc_w2, p_w2t, 128, 64, 12, 12);
    launch_wtrans(enc_w3, p_w3t, 128, 128, 3, 3);
    launch_wtrans(enc_rw1,            p_er1t,            64, 128, 3, 3);
    launch_wtrans(enc_rw1 + 64*128*9, p_er1t + 1152*64,  64, 128, 3, 3);
    launch_wtrans(enc_rw2,            p_er2t,            128, 64, 1, 1);
    launch_wtrans(enc_rw2 + 128*64,   p_er2t + 64*128,   128, 64, 1, 1);
    launch_wtrans(pre_w, p_pret, 64, 128, 1, 1);
    launch_wtrans(dec_w1, p_d1t, 128, 64, 3, 3);
    launch_wtrans(dec_rw1,            p_dr1t,            64, 128, 3, 3);
    launch_wtrans(dec_rw1 + 64*128*9, p_dr1t + 1152*64,  64, 128, 3, 3);
    launch_wtrans(dec_rw2,            p_dr2t,            128, 64, 1, 1);
    launch_wtrans(dec_rw2 + 128*64,   p_dr2t + 64*128,   128, 64, 1, 1);
    {
        int tot1 = 128*64*144;
        wtransT_kernel<<<(tot1+255)/256, 256>>>(dec_tw1, p_tw1t, 128, 64, 12, 12);
        int tot2 = 64*2*110;
        wtransT_kernel<<<(tot2+255)/256, 256>>>(dec_tw2, p_tw2t, 64, 2, 10, 11);
    }

    // ---- encoder ----
    {
        long tot = (long)NB*C0*H0*W0;
        nchw2nhwc_kernel<<<(unsigned)((tot+255)/256), 256>>>(x, p_x, NB, C0, H0, W0);
    }
    launch_im2col(p_x, p_A1, NB, H0, W0, C0, KH1, KW1, 8, 9, 1, 1, H1, W1, 0);
    launch_gemm(p_A1, p_w1t, p_h1, POS1, OC1, K1, enc_b1, 1, 0, 0);          // conv1 + relu

    launch_im2col(p_h1, p_col, NB, H1, W1, 64, 12, 12, 10, 10, 1, 1, H2, W2, 0);
    launch_gemm_splitk(p_col, p_w2t, p_hA, p_part, POS2, 128, K2, 8, enc_b2, 1, 0);   // conv2 + relu

    launch_im2col(p_hA, p_col, NB, H2, W2, 128, 3, 3, 1, 1, 1, 1, H2, W2, 0);
    launch_gemm_splitk(p_col, p_w3t, p_hB, p_part, POS2, 128, 1152, 8, enc_b3, 0, 0); // conv3

    for (int i = 0; i < 2; i++) {                                            // enc res stack
        launch_im2col(p_hB, p_col, NB, H2, W2, 128, 3, 3, 1, 1, 1, 1, H2, W2, 1);
        launch_gemm_splitk(p_col, p_er1t + i*1152*64, p_t64, p_part, POS2, 64, 1152, 8, 0, 1, 0);
        launch_gemm(p_t64, p_er2t + i*64*128, p_hB, POS2, 128, 64, 0, 0, 0, 1);
    }
    launch_gemm(p_hB, p_pret, p_z, POS2, 64, 128, pre_b, 0, 1, 0);           // pre (relu on input)

    // ---- VQ ----
    zero_kernel<<<1, KE>>>(p_counts, p_sqacc);
    esq_kernel<<<1, KE>>>(emb, p_esq);
    vq_kernel<<<POS2, 128>>>(p_z, emb, p_esq, p_idx, p_q, p_counts, p_sqacc);
    finalize_kernel<<<1, KE>>>(p_counts, p_sqacc, out, (long)out_size);

    // ---- decoder ----
    launch_im2col(p_q, p_col, NB, H2, W2, 64, 3, 3, 1, 1, 1, 1, H2, W2, 0);
    launch_gemm_splitk(p_col, p_d1t, p_hA, p_part, POS2, 128, 576, 4, dec_b1, 0, 0);  // dec conv1

    for (int i = 0; i < 2; i++) {                                            // dec res stack
        launch_im2col(p_hA, p_col, NB, H2, W2, 128, 3, 3, 1, 1, 1, 1, H2, W2, 1);
        launch_gemm_splitk(p_col, p_dr1t + i*1152*64, p_t64, p_part, POS2, 64, 1152, 8, 0, 1, 0);
        launch_gemm(p_t64, p_dr2t + i*64*128, p_hA, POS2, 128, 64, 0, 0, 0, 1);
    }

    // convT1: GEMM (relu on input) + gather (+bias, relu)
    launch_gemm(p_hA, p_tw1t, p_Y1, POS2, NT1, 128, 0, 0, 1, 0);
    gather_t1_kernel<<<(POSD*64 + 255)/256, 256>>>(p_Y1, dec_tb1, p_t1);

    // convT2: GEMM + gather (+bias) -> recon at out+1
    launch_gemm(p_t1, p_tw2t, p_Y2, POSD, NT2, 64, 0, 0, 0, 0);
    {
        long tot = (long)RECON_N;
        gather_recon_kernel<<<(unsigned)((tot+255)/256), 256>>>(p_Y2, dec_tb2, out + 1);
    }
}